// round 3
// baseline (speedup 1.0000x reference)
#include <cuda_runtime.h>

#define Bn 16
#define Nn 1024
#define Cc 64
#define Kk 5
#define KC 320      /* Kk*Cc */
#define Oo 64
#define Dd 10
#define WSZ 20480   /* KC*Oo */

// Scratch (static device allocations — allowed; runtime allocs are not).
__device__ float g_xg[(size_t)Bn * Nn * Kk * Cc];  // [b][n][k][c], ~21M floats
__device__ float g_W [(size_t)Nn * WSZ];           // [n][kc][o],  ~21M floats

// ---------------------------------------------------------------------------
// Copy x into the k=0 slot of g_xg. One float4 per thread.
// ---------------------------------------------------------------------------
__global__ __launch_bounds__(256) void copy_x_kernel(const float* __restrict__ x) {
    int i = blockIdx.x * 256 + threadIdx.x;      // 262144 float4s total
    int bn = i >> 4;                              // (b*Nn + n)
    int c4 = (i & 15) << 2;
    float4 v = *(const float4*)(x + (size_t)bn * Cc + c4);
    *(float4*)(g_xg + (size_t)bn * KC + c4) = v;
}

// ---------------------------------------------------------------------------
// One graph hop: Y[b,n,c] = sum_m A[b,n,m] * X[b,m,c]
// A = adj support slice [B][N][N]. Input is x (k_in<0) or g_xg slice k_in.
// Output always goes to g_xg slice k_out.
// Tiling: 64(M) x 64(N=C) x 32(K), 256 threads, 4x4 micro-tile per thread.
// ---------------------------------------------------------------------------
__global__ __launch_bounds__(256) void hop_gemm(const float* __restrict__ adj_s,
                                                const float* __restrict__ x,
                                                int k_in, int k_out) {
    const int b    = blockIdx.y;
    const int row0 = blockIdx.x * 64;

    const float* A = adj_s + (size_t)b * Nn * Nn;
    const float* X;
    int ldx;
    if (k_in < 0) { X = x    + (size_t)b * Nn * Cc;               ldx = Cc; }
    else          { X = g_xg + (size_t)b * Nn * KC + k_in * Cc;   ldx = KC; }
    float* Y = g_xg + (size_t)b * Nn * KC + k_out * Cc;

    __shared__ float As[64][33];   // +1 pad: conflict-free column reads
    __shared__ float Bs[32][64];

    const int tid = threadIdx.x;
    const int ty4 = (tid >> 4) << 2;   // row group 0..60
    const int tx4 = (tid & 15) << 2;   // col group 0..60

    float acc[4][4];
#pragma unroll
    for (int i = 0; i < 4; ++i)
#pragma unroll
        for (int j = 0; j < 4; ++j) acc[i][j] = 0.f;

    for (int k0 = 0; k0 < Nn; k0 += 32) {
        // Load A tile: 64 rows x 32 cols = 512 float4s
#pragma unroll
        for (int p = 0; p < 2; ++p) {
            int idx = tid + p * 256;
            int r = idx >> 3, c4 = (idx & 7) << 2;
            float4 v = *(const float4*)(A + (size_t)(row0 + r) * Nn + k0 + c4);
            As[r][c4 + 0] = v.x; As[r][c4 + 1] = v.y;
            As[r][c4 + 2] = v.z; As[r][c4 + 3] = v.w;
        }
        // Load X tile: 32 rows x 64 cols = 512 float4s
#pragma unroll
        for (int p = 0; p < 2; ++p) {
            int idx = tid + p * 256;
            int r = idx >> 4, c4 = (idx & 15) << 2;
            float4 v = *(const float4*)(X + (size_t)(k0 + r) * ldx + c4);
            *(float4*)&Bs[r][c4] = v;
        }
        __syncthreads();

#pragma unroll
        for (int kk = 0; kk < 32; ++kk) {
            float a0 = As[ty4 + 0][kk], a1 = As[ty4 + 1][kk];
            float a2 = As[ty4 + 2][kk], a3 = As[ty4 + 3][kk];
            float b0 = Bs[kk][tx4 + 0], b1 = Bs[kk][tx4 + 1];
            float b2 = Bs[kk][tx4 + 2], b3 = Bs[kk][tx4 + 3];
            acc[0][0] += a0 * b0; acc[0][1] += a0 * b1; acc[0][2] += a0 * b2; acc[0][3] += a0 * b3;
            acc[1][0] += a1 * b0; acc[1][1] += a1 * b1; acc[1][2] += a1 * b2; acc[1][3] += a1 * b3;
            acc[2][0] += a2 * b0; acc[2][1] += a2 * b1; acc[2][2] += a2 * b2; acc[2][3] += a2 * b3;
            acc[3][0] += a3 * b0; acc[3][1] += a3 * b1; acc[3][2] += a3 * b2; acc[3][3] += a3 * b3;
        }
        __syncthreads();
    }

#pragma unroll
    for (int i = 0; i < 4; ++i) {
        float4 v = make_float4(acc[i][0], acc[i][1], acc[i][2], acc[i][3]);
        *(float4*)(Y + (size_t)(row0 + ty4 + i) * KC + tx4) = v;
    }
}

// ---------------------------------------------------------------------------
// W[n, j] = sum_d emb[n,d] * wp[d, j],   j in [0, 20480)
// j-chunked: each block caches its wp slice (10 x 64) in smem ONCE, then
// sweeps all 1024 nodes -> wp global traffic is 3.3 MB total, not 820 MB.
// ---------------------------------------------------------------------------
#define JC 64
__global__ __launch_bounds__(256) void make_weights(const float* __restrict__ emb,
                                                    const float* __restrict__ wp) {
    __shared__ float wpS[Dd][JC];
    const int j0  = blockIdx.x * JC;     // 320 blocks
    const int tid = threadIdx.x;

    for (int p = tid; p < Dd * JC; p += 256)
        wpS[p / JC][p % JC] = wp[(size_t)(p / JC) * WSZ + j0 + (p % JC)];
    __syncthreads();

    const int jj = tid & 63;
    const int tl = tid >> 6;             // 0..3
    for (int n = tl; n < Nn; n += 4) {
        const float* e = emb + n * Dd;
        float s = 0.f;
#pragma unroll
        for (int d = 0; d < Dd; ++d) s += __ldg(&e[d]) * wpS[d][jj];
        g_W[(size_t)n * WSZ + j0 + jj] = s;
    }
}

// ---------------------------------------------------------------------------
// Per-node: out[b,n,o] = sum_kc xg[b,n,kc] * W[n,kc,o] + sum_d emb[n,d]*bp[d,o]
// One block per node. Thread = (bq = tid/64 in 0..3, o = tid%64); each thread
// accumulates 4 batches. Each warp has a fixed bq -> xs reads are broadcasts.
// ---------------------------------------------------------------------------
__global__ __launch_bounds__(256) void final_contract(const float* __restrict__ emb,
                                                      const float* __restrict__ bias_pool,
                                                      float* __restrict__ out) {
    const int n   = blockIdx.x;
    const int tid = threadIdx.x;
    __shared__ float xs[Bn][KC];   // 20 KB
    __shared__ float ws[16][Oo];   // 4 KB (current W chunk)

    // Stage all 16 batch vectors for this node: 1280 float4s
    for (int p = tid; p < Bn * KC / 4; p += 256) {
        int b = p / 80, c4 = (p % 80) << 2;
        float4 v = *(const float4*)(g_xg + ((size_t)b * Nn + n) * KC + c4);
        *(float4*)&xs[b][c4] = v;
    }

    const int o  = tid & 63;
    const int bq = tid >> 6;       // 0..3
    float acc0 = 0.f, acc1 = 0.f, acc2 = 0.f, acc3 = 0.f;
    const float* Wn = g_W + (size_t)n * WSZ;

    for (int kc0 = 0; kc0 < KC; kc0 += 16) {
        __syncthreads();           // xs ready (1st iter) / prev ws reads done
        {
            int r = tid >> 4, c4 = (tid & 15) << 2;
            *(float4*)&ws[r][c4] = *(const float4*)(Wn + (size_t)(kc0 + r) * Oo + c4);
        }
        __syncthreads();
#pragma unroll
        for (int t = 0; t < 16; ++t) {
            float w = ws[t][o];
            acc0 += xs[bq +  0][kc0 + t] * w;
            acc1 += xs[bq +  4][kc0 + t] * w;
            acc2 += xs[bq +  8][kc0 + t] * w;
            acc3 += xs[bq + 12][kc0 + t] * w;
        }
    }

    float bias = 0.f;
#pragma unroll
    for (int d = 0; d < Dd; ++d) bias += emb[n * Dd + d] * bias_pool[d * Oo + o];

    out[((size_t)(bq +  0) * Nn + n) * Oo + o] = acc0 + bias;
    out[((size_t)(bq +  4) * Nn + n) * Oo + o] = acc1 + bias;
    out[((size_t)(bq +  8) * Nn + n) * Oo + o] = acc2 + bias;
    out[((size_t)(bq + 12) * Nn + n) * Oo + o] = acc3 + bias;
}

// ---------------------------------------------------------------------------
extern "C" void kernel_launch(void* const* d_in, const int* in_sizes, int n_in,
                              void* d_out, int out_size) {
    const float* x         = (const float*)d_in[0];  // [16,1024,64]
    const float* adj       = (const float*)d_in[1];  // [2,16,1024,1024]
    const float* emb       = (const float*)d_in[2];  // [1024,10]
    const float* wp        = (const float*)d_in[3];  // [10,5,64,64]
    const float* bias_pool = (const float*)d_in[4];  // [10,64]
    float*       out       = (float*)d_out;          // [16,1024,64]

    const float* adj0 = adj;
    const float* adj1 = adj + (size_t)Bn * Nn * Nn;

    copy_x_kernel<<<1024, 256>>>(x);          // xg k=0
    make_weights <<<WSZ / JC, 256>>>(emb, wp);

    dim3 g(Nn / 64, Bn);
    hop_gemm<<<g, 256>>>(adj0, x, -1, 1);     // s0 hop1
    hop_gemm<<<g, 256>>>(adj0, x,  1, 2);     // s0 hop2
    hop_gemm<<<g, 256>>>(adj1, x, -1, 3);     // s1 hop1
    hop_gemm<<<g, 256>>>(adj1, x,  3, 4);     // s1 hop2

    final_contract<<<1024, 256>>>(emb, bias_pool, out);
}

// round 5
// speedup vs baseline: 1.2214x; 1.2214x over previous
#include <cuda_runtime.h>

#define Bn 16
#define Nn 1024
#define Cc 64
#define Kk 5
#define KC 320      /* Kk*Cc */
#define Oo 64
#define Dd 10
#define WSZ 20480   /* KC*Oo */

// Scratch (static device arrays — runtime allocation is forbidden).
__device__ float g_xg[(size_t)Bn * Nn * Kk * Cc];  // [b][n][k][c]
__device__ float g_W [(size_t)Nn * WSZ];           // [n][kc][o]

// ---------------------------------------------------------------------------
// Copy x into the k=0 slot of g_xg. One float4 per thread.
// ---------------------------------------------------------------------------
__global__ __launch_bounds__(256) void copy_x_kernel(const float* __restrict__ x) {
    int i = blockIdx.x * 256 + threadIdx.x;      // 262144 float4s total
    int bn = i >> 4;
    int c4 = (i & 15) << 2;
    float4 v = *(const float4*)(x + (size_t)bn * Cc + c4);
    *(float4*)(g_xg + (size_t)bn * KC + c4) = v;
}

// ---------------------------------------------------------------------------
// One hop stage over BOTH supports: Y[b,n,c] = sum_m A[s,b,n,m] * X[b,m,c]
// grid = (N/64, B, 2 supports). Slice indexing: in = kin_base + 2*s (or x if
// kin_base<0), out = kout_base + 2*s.
// Tiling: 64x64x32, 256 threads, 4x4 micro-tile, float4 LDS both operands,
// register prefetch of the next K-tile over the compute phase.
// ---------------------------------------------------------------------------
__global__ __launch_bounds__(256) void hop_gemm(const float* __restrict__ adj,
                                                const float* __restrict__ x,
                                                int kin_base, int kout_base) {
    const int s    = blockIdx.z;
    const int b    = blockIdx.y;
    const int row0 = blockIdx.x * 64;

    const float* A = adj + ((size_t)s * Bn + b) * Nn * Nn;
    const float* X;
    int ldx;
    if (kin_base < 0) { X = x    + (size_t)b * Nn * Cc;                       ldx = Cc; }
    else              { X = g_xg + (size_t)b * Nn * KC + (kin_base + 2*s)*Cc; ldx = KC; }
    float* Y = g_xg + (size_t)b * Nn * KC + (kout_base + 2*s) * Cc;

    __shared__ float As[64][68];   // row-major [row][k], pad 68 (16B-aligned rows)
    __shared__ float Bs[32][64];   // [k][col]

    const int tid = threadIdx.x;
    const int ty  = tid >> 4;          // 0..15 -> rows 4ty..4ty+3
    const int tx  = tid & 15;          // 0..15 -> cols 4tx..4tx+3

    // Load mapping. A tile 64x32 = 512 f4: r=idx>>3 (0..63), c4=(idx&7)*4.
    // B tile 32x64 = 512 f4: r=idx>>4 (0..31), c4=(idx&15)*4.
    const int ra  = tid >> 3, ca = (tid & 7) << 2;
    const int rb  = tid >> 4, cb = (tid & 15) << 2;
    const float* Ap = A + (size_t)(row0 + ra) * Nn + ca;    // +32 rows for chunk 1
    const float* Bp = X + (size_t)rb * ldx + cb;            // +16 rows for chunk 1

    float acc[4][4];
#pragma unroll
    for (int i = 0; i < 4; ++i)
#pragma unroll
        for (int j = 0; j < 4; ++j) acc[i][j] = 0.f;

    // Prefetch tile 0
    float4 pa0 = *(const float4*)(Ap);
    float4 pa1 = *(const float4*)(Ap + (size_t)32 * Nn);
    float4 pb0 = *(const float4*)(Bp);
    float4 pb1 = *(const float4*)(Bp + (size_t)16 * ldx);

    for (int k0 = 0; k0 < Nn; k0 += 32) {
        // Store current tile to smem
        *(float4*)&As[ra     ][ca] = pa0;
        *(float4*)&As[ra + 32][ca] = pa1;
        *(float4*)&Bs[rb     ][cb] = pb0;
        *(float4*)&Bs[rb + 16][cb] = pb1;
        __syncthreads();

        // Issue next tile's LDGs (latency overlapped with compute)
        if (k0 + 32 < Nn) {
            pa0 = *(const float4*)(Ap + k0 + 32);
            pa1 = *(const float4*)(Ap + (size_t)32 * Nn + k0 + 32);
            pb0 = *(const float4*)(Bp + (size_t)(k0 + 32) * ldx);
            pb1 = *(const float4*)(Bp + (size_t)(k0 + 48) * ldx);
        }

#pragma unroll
        for (int kk4 = 0; kk4 < 32; kk4 += 4) {
            float4 av[4], bv[4];
#pragma unroll
            for (int i = 0; i < 4; ++i) av[i] = *(const float4*)&As[4*ty + i][kk4];
#pragma unroll
            for (int j = 0; j < 4; ++j) bv[j] = *(const float4*)&Bs[kk4 + j][4*tx];
#pragma unroll
            for (int i = 0; i < 4; ++i) {
                acc[i][0] += av[i].x * bv[0].x; acc[i][1] += av[i].x * bv[0].y;
                acc[i][2] += av[i].x * bv[0].z; acc[i][3] += av[i].x * bv[0].w;
                acc[i][0] += av[i].y * bv[1].x; acc[i][1] += av[i].y * bv[1].y;
                acc[i][2] += av[i].y * bv[1].z; acc[i][3] += av[i].y * bv[1].w;
                acc[i][0] += av[i].z * bv[2].x; acc[i][1] += av[i].z * bv[2].y;
                acc[i][2] += av[i].z * bv[2].z; acc[i][3] += av[i].z * bv[2].w;
                acc[i][0] += av[i].w * bv[3].x; acc[i][1] += av[i].w * bv[3].y;
                acc[i][2] += av[i].w * bv[3].z; acc[i][3] += av[i].w * bv[3].w;
            }
        }
        __syncthreads();
    }

#pragma unroll
    for (int i = 0; i < 4; ++i) {
        float4 v = make_float4(acc[i][0], acc[i][1], acc[i][2], acc[i][3]);
        *(float4*)(Y + (size_t)(row0 + 4*ty + i) * KC + 4*tx) = v;
    }
}

// ---------------------------------------------------------------------------
// W[n, j] = sum_d emb[n,d] * wp[d, j]. grid (320, 4): x = 64-wide j chunk,
// y = 256-node chunk. wp slice and emb chunk staged in smem once per block.
// ---------------------------------------------------------------------------
#define JC 64
__global__ __launch_bounds__(256) void make_weights(const float* __restrict__ emb,
                                                    const float* __restrict__ wp) {
    __shared__ float wpS[Dd][JC];
    __shared__ float eS[256][Dd];
    const int j0  = blockIdx.x * JC;
    const int n0  = blockIdx.y * 256;
    const int tid = threadIdx.x;

    for (int p = tid; p < Dd * JC; p += 256)
        wpS[p / JC][p % JC] = wp[(size_t)(p / JC) * WSZ + j0 + (p % JC)];
    for (int p = tid; p < 256 * Dd; p += 256)
        eS[p / Dd][p % Dd] = emb[(size_t)(n0 + p / Dd) * Dd + (p % Dd)];
    __syncthreads();

    const int jj = tid & 63;
    const int tl = tid >> 6;             // 0..3
    for (int i = 0; i < 64; ++i) {
        int nl = i * 4 + tl;
        float s = 0.f;
#pragma unroll
        for (int d = 0; d < Dd; ++d) s += eS[nl][d] * wpS[d][jj];
        g_W[(size_t)(n0 + nl) * WSZ + j0 + jj] = s;
    }
}

// ---------------------------------------------------------------------------
// out[b,n,o] = sum_kc xg[b,n,kc]*W[n,kc,o] + sum_d emb[n,d]*bp[d,o]
// One block per node. Thread = (b = tid>>4, o4 = (tid&15)*4): 4 o-outputs per
// thread, 4 FFMA per {LDS.128 ws + broadcast LDS xs}.
// ---------------------------------------------------------------------------
__global__ __launch_bounds__(256) void final_contract(const float* __restrict__ emb,
                                                      const float* __restrict__ bias_pool,
                                                      float* __restrict__ out) {
    const int n   = blockIdx.x;
    const int tid = threadIdx.x;
    __shared__ float xs[Bn][KC];   // 20 KB
    __shared__ float ws[32][Oo];   // 8 KB per W chunk

    // Stage all 16 batch vectors for this node: 1280 float4s
    for (int p = tid; p < Bn * KC / 4; p += 256) {
        int b = p / 80, c4 = (p % 80) << 2;
        *(float4*)&xs[b][c4] =
            *(const float4*)(g_xg + ((size_t)b * Nn + n) * KC + c4);
    }

    const int b  = tid >> 4;           // 0..15
    const int o4 = (tid & 15) << 2;    // 0..60
    float a0 = 0.f, a1 = 0.f, a2 = 0.f, a3 = 0.f;
    const float* Wn = g_W + (size_t)n * WSZ;

    for (int kc0 = 0; kc0 < KC; kc0 += 32) {
        __syncthreads();               // xs ready (1st) / prev ws reads done
#pragma unroll
        for (int p = 0; p < 2; ++p) {
            int idx = tid + p * 256;
            int r = idx >> 4, c4 = (idx & 15) << 2;
            *(float4*)&ws[r][c4] = *(const float4*)(Wn + (size_t)(kc0 + r) * Oo + c4);
        }
        __syncthreads();
#pragma unroll
        for (int t = 0; t < 32; ++t) {
            float xv = xs[b][kc0 + t];
            float4 w = *(const float4*)&ws[t][o4];
            a0 += xv * w.x; a1 += xv * w.y; a2 += xv * w.z; a3 += xv * w.w;
        }
    }

    float b0 = 0.f, b1 = 0.f, b2 = 0.f, b3 = 0.f;
#pragma unroll
    for (int d = 0; d < Dd; ++d) {
        float e = emb[n * Dd + d];
        const float* bp = bias_pool + d * Oo + o4;
        b0 += e * bp[0]; b1 += e * bp[1]; b2 += e * bp[2]; b3 += e * bp[3];
    }

    float4 v = make_float4(a0 + b0, a1 + b1, a2 + b2, a3 + b3);
    *(float4*)(out + ((size_t)b * Nn + n) * Oo + o4) = v;
}

// ---------------------------------------------------------------------------
extern "C" void kernel_launch(void* const* d_in, const int* in_sizes, int n_in,
                              void* d_out, int out_size) {
    const float* x         = (const float*)d_in[0];  // [16,1024,64]
    const float* adj       = (const float*)d_in[1];  // [2,16,1024,1024]
    const float* emb       = (const float*)d_in[2];  // [1024,10]
    const float* wp        = (const float*)d_in[3];  // [10,5,64,64]
    const float* bias_pool = (const float*)d_in[4];  // [10,64]
    float*       out       = (float*)d_out;          // [16,1024,64]

    copy_x_kernel<<<1024, 256>>>(x);
    make_weights <<<dim3(WSZ / JC, 4), 256>>>(emb, wp);

    dim3 g(Nn / 64, Bn, 2);
    hop_gemm<<<g, 256>>>(adj, x, -1, 1);   // stage 1: both supports, x -> slice 1+2s
    hop_gemm<<<g, 256>>>(adj, x,  1, 2);   // stage 2: slice 1+2s -> slice 2+2s

    final_contract<<<1024, 256>>>(emb, bias_pool, out);
}